// round 5
// baseline (speedup 1.0000x reference)
#include <cuda_runtime.h>
#include <math.h>

#define DIMN   1024
#define S_LEN  2048
#define BATCH  2
#define NHEAD  16     // 2H attention heads (q/k), dim 64
#define HD     64
#define VD     128    // v head dim (2*hd)
#define M_TOT  (BATCH*S_LEN)   // 4096

#define LAMBDA_INIT 0.70082066706704805f

// ---------------- scratch (static device memory; no runtime allocs) ----------
__device__ float g_q[(size_t)BATCH*S_LEN*DIMN];
__device__ float g_k[(size_t)BATCH*S_LEN*DIMN];
__device__ float g_v[(size_t)BATCH*S_LEN*DIMN];
__device__ float g_oj[(size_t)BATCH*NHEAD*S_LEN*VD];   // per-attn-head O
__device__ float g_att[(size_t)BATCH*S_LEN*DIMN];      // combined, pre-Wo
__device__ float g_lambda;

// ---------------- lambda ------------------------------------------------------
__global__ void lambda_kernel(const float* __restrict__ lq1, const float* __restrict__ lk1,
                              const float* __restrict__ lq2, const float* __restrict__ lk2) {
    if (threadIdx.x == 0) {
        float s1 = 0.f, s2 = 0.f;
        for (int i = 0; i < HD; i++) { s1 += lq1[i]*lk1[i]; s2 += lq2[i]*lk2[i]; }
        g_lambda = expf(s1) - expf(s2) + LAMBDA_INIT;
    }
}

// ---------------- NT GEMM: C[m,n] = alpha * sum_k A[m,k]*B[n,k] ---------------
// BM=BN=128, BK=16, 256 threads, 8x8 register tile, register-staged prefetch.
__global__ __launch_bounds__(256) void gemm_nt(const float* __restrict__ A,
                                               const float* __restrict__ B,
                                               float* __restrict__ C,
                                               int M, int N, int K, float alpha) {
    __shared__ float As[128][20];
    __shared__ float Bs[128][20];
    const int tid = threadIdx.x;
    const int ty = tid >> 4, tx = tid & 15;
    const int bm0 = blockIdx.y * 128, bn0 = blockIdx.x * 128;

    // each thread stages 2 float4 per matrix per k-tile
    const int ldr  = (tid + 0)   >> 2;          // rows for u=0,1
    const int ldr2 = (tid + 256) >> 2;
    const int ldc  = (tid & 3) << 2;

    float acc[8][8];
#pragma unroll
    for (int i = 0; i < 8; i++)
#pragma unroll
        for (int j = 0; j < 8; j++) acc[i][j] = 0.f;

    // prefetch first tile into registers
    float4 ra0 = *(const float4*)&A[(size_t)(bm0 + ldr ) * K + ldc];
    float4 ra1 = *(const float4*)&A[(size_t)(bm0 + ldr2) * K + ldc];
    float4 rb0 = *(const float4*)&B[(size_t)(bn0 + ldr ) * K + ldc];
    float4 rb1 = *(const float4*)&B[(size_t)(bn0 + ldr2) * K + ldc];

    for (int k0 = 0; k0 < K; k0 += 16) {
        // commit staged registers to smem
        *(float4*)&As[ldr ][ldc] = ra0;
        *(float4*)&As[ldr2][ldc] = ra1;
        *(float4*)&Bs[ldr ][ldc] = rb0;
        *(float4*)&Bs[ldr2][ldc] = rb1;
        __syncthreads();

        // issue next tile's global loads (overlap with FMA body below)
        if (k0 + 16 < K) {
            int kn = k0 + 16;
            ra0 = *(const float4*)&A[(size_t)(bm0 + ldr ) * K + kn + ldc];
            ra1 = *(const float4*)&A[(size_t)(bm0 + ldr2) * K + kn + ldc];
            rb0 = *(const float4*)&B[(size_t)(bn0 + ldr ) * K + kn + ldc];
            rb1 = *(const float4*)&B[(size_t)(bn0 + ldr2) * K + kn + ldc];
        }

#pragma unroll
        for (int kk = 0; kk < 16; kk += 4) {
            float4 a[8], b[8];
#pragma unroll
            for (int i = 0; i < 8; i++) a[i] = *(float4*)&As[ty + 16 * i][kk];
#pragma unroll
            for (int j = 0; j < 8; j++) b[j] = *(float4*)&Bs[tx + 16 * j][kk];
#pragma unroll
            for (int i = 0; i < 8; i++)
#pragma unroll
                for (int j = 0; j < 8; j++)
                    acc[i][j] += a[i].x*b[j].x + a[i].y*b[j].y + a[i].z*b[j].z + a[i].w*b[j].w;
        }
        __syncthreads();
    }
#pragma unroll
    for (int i = 0; i < 8; i++)
#pragma unroll
        for (int j = 0; j < 8; j++)
            C[(size_t)(bm0 + ty + 16 * i) * N + bn0 + tx + 16 * j] = alpha * acc[i][j];
}

// ---------------- flash attention (one attn head, causal) --------------------
// grid: (S/64, NHEAD, BATCH). 256 threads (16x16). BM=BN=64.
// smem: Qs[64][68] Ks[64][68] Ps[64][68] Vs[64][132]  = 86016 bytes
#define FLASH_SMEM_FLOATS (3 * 64 * 68 + 64 * 132)
#define FLASH_SMEM_BYTES  (FLASH_SMEM_FLOATS * 4)

__global__ __launch_bounds__(256) void flash_kernel(const float* __restrict__ q,
                                                    const float* __restrict__ k,
                                                    const float* __restrict__ v,
                                                    float* __restrict__ oj) {
    extern __shared__ float sm[];
    float (*Qs)[68]  = (float (*)[68])sm;
    float (*Ks)[68]  = (float (*)[68])(sm + 64 * 68);
    float (*Ps)[68]  = (float (*)[68])(sm + 2 * 64 * 68);
    float (*Vs)[132] = (float (*)[132])(sm + 3 * 64 * 68);

    const int tid = threadIdx.x;
    const int ty = tid >> 4, tx = tid & 15;
    const int qb = blockIdx.x;      // query block (64 rows)
    const int h  = blockIdx.y;      // attn head 0..15
    const int b  = blockIdx.z;
    const int hv = h >> 1;

    const float* qbase = q + ((size_t)(b * S_LEN + qb * 64)) * DIMN + h * HD;
    const float* kbase = k + (size_t)b * S_LEN * DIMN + h * HD;
    const float* vbase = v + (size_t)b * S_LEN * DIMN + hv * VD;

    // load Q tile: 64 rows x 64 floats (16 float4/row)
#pragma unroll
    for (int u = 0; u < 4; u++) {
        int idx = tid + u * 256;        // 0..1023
        int row = idx >> 4;
        int c4  = (idx & 15) << 2;
        *(float4*)&Qs[row][c4] = *(const float4*)&qbase[(size_t)row * DIMN + c4];
    }

    float m[4], l[4], o[4][8];
#pragma unroll
    for (int i = 0; i < 4; i++) {
        m[i] = -1e30f; l[i] = 0.f;
#pragma unroll
        for (int j = 0; j < 8; j++) o[i][j] = 0.f;
    }

    for (int kt = 0; kt <= qb; kt++) {
        __syncthreads();   // also orders Q-tile writes before first compute
        // load K tile (64x64) and V tile (64x128)
#pragma unroll
        for (int u = 0; u < 4; u++) {
            int idx = tid + u * 256;
            int row = idx >> 4;
            int c4  = (idx & 15) << 2;
            *(float4*)&Ks[row][c4] = *(const float4*)&kbase[(size_t)(kt * 64 + row) * DIMN + c4];
        }
#pragma unroll
        for (int u = 0; u < 8; u++) {
            int idx = tid + u * 256;    // 0..2047
            int row = idx >> 5;
            int c4  = (idx & 31) << 2;
            *(float4*)&Vs[row][c4] = *(const float4*)&vbase[(size_t)(kt * 64 + row) * DIMN + c4];
        }
        __syncthreads();

        // S = Q K^T  (q already scaled by 1/8)
        float s[4][4];
#pragma unroll
        for (int i = 0; i < 4; i++)
#pragma unroll
            for (int j = 0; j < 4; j++) s[i][j] = 0.f;
#pragma unroll
        for (int kk = 0; kk < 64; kk += 4) {
            float4 a[4], bb[4];
#pragma unroll
            for (int i = 0; i < 4; i++) a[i]  = *(float4*)&Qs[ty + 16 * i][kk];
#pragma unroll
            for (int j = 0; j < 4; j++) bb[j] = *(float4*)&Ks[tx + 16 * j][kk];
#pragma unroll
            for (int i = 0; i < 4; i++)
#pragma unroll
                for (int j = 0; j < 4; j++)
                    s[i][j] += a[i].x*bb[j].x + a[i].y*bb[j].y + a[i].z*bb[j].z + a[i].w*bb[j].w;
        }
        if (kt == qb) {
#pragma unroll
            for (int i = 0; i < 4; i++)
#pragma unroll
                for (int j = 0; j < 4; j++)
                    if ((tx + 16 * j) > (ty + 16 * i)) s[i][j] = -1e30f;
        }

        // online softmax per row (row owned by 16 tx-threads; shfl width 16)
#pragma unroll
        for (int i = 0; i < 4; i++) {
            float mt = s[i][0];
#pragma unroll
            for (int j = 1; j < 4; j++) mt = fmaxf(mt, s[i][j]);
#pragma unroll
            for (int off = 8; off > 0; off >>= 1)
                mt = fmaxf(mt, __shfl_xor_sync(0xffffffffu, mt, off, 16));
            float mn = fmaxf(m[i], mt);
            float sc = __expf(m[i] - mn);
            float ps = 0.f;
#pragma unroll
            for (int j = 0; j < 4; j++) { s[i][j] = __expf(s[i][j] - mn); ps += s[i][j]; }
#pragma unroll
            for (int off = 8; off > 0; off >>= 1)
                ps += __shfl_xor_sync(0xffffffffu, ps, off, 16);
            l[i] = l[i] * sc + ps;
#pragma unroll
            for (int j = 0; j < 8; j++) o[i][j] *= sc;
            m[i] = mn;
#pragma unroll
            for (int j = 0; j < 4; j++) Ps[ty + 16 * i][tx + 16 * j] = s[i][j];
        }
        __syncthreads();

        // O += P @ V   (O cols: tx*4..+3 and 64+tx*4..+3)
#pragma unroll
        for (int kk = 0; kk < 64; kk += 4) {
            float4 p4[4];
#pragma unroll
            for (int i = 0; i < 4; i++) p4[i] = *(float4*)&Ps[ty + 16 * i][kk];
#pragma unroll
            for (int kq = 0; kq < 4; kq++) {
                float4 v0 = *(float4*)&Vs[kk + kq][tx * 4];
                float4 v1 = *(float4*)&Vs[kk + kq][64 + tx * 4];
#pragma unroll
                for (int i = 0; i < 4; i++) {
                    float pk = (kq == 0) ? p4[i].x : (kq == 1) ? p4[i].y : (kq == 2) ? p4[i].z : p4[i].w;
                    o[i][0] += pk * v0.x; o[i][1] += pk * v0.y;
                    o[i][2] += pk * v0.z; o[i][3] += pk * v0.w;
                    o[i][4] += pk * v1.x; o[i][5] += pk * v1.y;
                    o[i][6] += pk * v1.z; o[i][7] += pk * v1.w;
                }
            }
        }
    }

    // epilogue: normalize and store to g_oj[b, h, s, 0:128]
    float* obase = oj + (((size_t)(b * NHEAD + h)) * S_LEN + qb * 64) * VD;
#pragma unroll
    for (int i = 0; i < 4; i++) {
        float inv = 1.f / l[i];
        int row = ty + 16 * i;
        float4 r0 = make_float4(o[i][0]*inv, o[i][1]*inv, o[i][2]*inv, o[i][3]*inv);
        float4 r1 = make_float4(o[i][4]*inv, o[i][5]*inv, o[i][6]*inv, o[i][7]*inv);
        *(float4*)&obase[(size_t)row * VD + tx * 4]      = r0;
        *(float4*)&obase[(size_t)row * VD + 64 + tx * 4] = r1;
    }
}

// ---------------- combine pairs + RMSNorm -------------------------------------
// grid: B*S*8 blocks of 128 threads. block -> (b, s, hv); thread -> d in [0,128)
__global__ void combine_kernel(const float* __restrict__ oj, float* __restrict__ att) {
    const int bid = blockIdx.x;
    const int hv = bid & 7;
    const int s  = (bid >> 3) & (S_LEN - 1);
    const int b  = bid >> 14;
    const int d  = threadIdx.x;

    const float lam = g_lambda;
    size_t i0 = (((size_t)(b * NHEAD + 2 * hv)) * S_LEN + s) * VD + d;
    size_t i1 = i0 + (size_t)S_LEN * VD;
    float val = oj[i0] - lam * oj[i1];

    float v2 = val * val;
#pragma unroll
    for (int off = 16; off > 0; off >>= 1)
        v2 += __shfl_xor_sync(0xffffffffu, v2, off);
    __shared__ float red[4];
    if ((d & 31) == 0) red[d >> 5] = v2;
    __syncthreads();
    float tot = red[0] + red[1] + red[2] + red[3];
    float rms = rsqrtf(tot * (1.0f / 128.0f) + 1e-5f);
    att[((size_t)(b * S_LEN) + s) * DIMN + hv * VD + d] = val * rms * (1.0f - LAMBDA_INIT);
}

// ---------------- launch ------------------------------------------------------
extern "C" void kernel_launch(void* const* d_in, const int* in_sizes, int n_in,
                              void* d_out, int out_size) {
    const float* x   = (const float*)d_in[0];
    const float* Wq  = (const float*)d_in[1];
    const float* Wk  = (const float*)d_in[2];
    const float* Wv  = (const float*)d_in[3];
    const float* Wo  = (const float*)d_in[4];
    const float* lq1 = (const float*)d_in[5];
    const float* lk1 = (const float*)d_in[6];
    const float* lq2 = (const float*)d_in[7];
    const float* lk2 = (const float*)d_in[8];
    float* out = (float*)d_out;

    float *q_p, *k_p, *v_p, *oj_p, *att_p;
    cudaGetSymbolAddress((void**)&q_p,   g_q);
    cudaGetSymbolAddress((void**)&k_p,   g_k);
    cudaGetSymbolAddress((void**)&v_p,   g_v);
    cudaGetSymbolAddress((void**)&oj_p,  g_oj);
    cudaGetSymbolAddress((void**)&att_p, g_att);

    cudaFuncSetAttribute(flash_kernel, cudaFuncAttributeMaxDynamicSharedMemorySize,
                         FLASH_SMEM_BYTES);

    lambda_kernel<<<1, 32>>>(lq1, lk1, lq2, lk2);

    dim3 ggrid(DIMN / 128, M_TOT / 128);
    gemm_nt<<<ggrid, 256>>>(x, Wq, q_p, M_TOT, DIMN, DIMN, 0.125f);  // hd^-0.5
    gemm_nt<<<ggrid, 256>>>(x, Wk, k_p, M_TOT, DIMN, DIMN, 1.0f);
    gemm_nt<<<ggrid, 256>>>(x, Wv, v_p, M_TOT, DIMN, DIMN, 1.0f);

    dim3 fgrid(S_LEN / 64, NHEAD, BATCH);
    flash_kernel<<<fgrid, 256, FLASH_SMEM_BYTES>>>(q_p, k_p, v_p, oj_p);

    combine_kernel<<<BATCH * S_LEN * 8, 128>>>(oj_p, att_p);

    gemm_nt<<<ggrid, 256>>>(att_p, Wo, out, M_TOT, DIMN, DIMN, 1.0f);
}

// round 7
// speedup vs baseline: 1.9426x; 1.9426x over previous
#include <cuda_runtime.h>
#include <math.h>
#include <stdint.h>

#define DIMN   1024
#define S_LEN  2048
#define BATCH  2
#define NHEAD  16     // 2H attention heads (q/k), dim 64
#define HD     64
#define VD     128    // v head dim (2*hd)
#define M_TOT  (BATCH*S_LEN)   // 4096

#define LAMBDA_INIT 0.70082066706704805f

// ---------------- scratch (static device memory; no runtime allocs) ----------
__device__ float g_q[(size_t)BATCH*S_LEN*DIMN];
__device__ float g_k[(size_t)BATCH*S_LEN*DIMN];
__device__ float g_v[(size_t)BATCH*S_LEN*DIMN];
__device__ float g_oj[(size_t)BATCH*NHEAD*S_LEN*VD];   // per-attn-head O
__device__ float g_att[(size_t)BATCH*S_LEN*DIMN];      // combined, pre-Wo
__device__ float g_lambda;

// ---------------- lambda ------------------------------------------------------
__global__ void lambda_kernel(const float* __restrict__ lq1, const float* __restrict__ lk1,
                              const float* __restrict__ lq2, const float* __restrict__ lk2) {
    if (threadIdx.x == 0) {
        float s1 = 0.f, s2 = 0.f;
        for (int i = 0; i < HD; i++) { s1 += lq1[i]*lk1[i]; s2 += lq2[i]*lk2[i]; }
        g_lambda = expf(s1) - expf(s2) + LAMBDA_INIT;
    }
}

// ---------------- tf32 mma helpers -------------------------------------------
__device__ __forceinline__ uint32_t f2tf32(float x) {
    uint32_t r;
    asm("cvt.rna.tf32.f32 %0, %1;" : "=r"(r) : "f"(x));
    return r;
}

__device__ __forceinline__ void mma_tf32(float* c,
                                         uint32_t a0, uint32_t a1, uint32_t a2, uint32_t a3,
                                         uint32_t b0, uint32_t b1) {
    asm volatile("mma.sync.aligned.m16n8k8.row.col.f32.tf32.tf32.f32 "
                 "{%0,%1,%2,%3}, {%4,%5,%6,%7}, {%8,%9}, {%0,%1,%2,%3};\n"
                 : "+f"(c[0]), "+f"(c[1]), "+f"(c[2]), "+f"(c[3])
                 : "r"(a0), "r"(a1), "r"(a2), "r"(a3), "r"(b0), "r"(b1));
}

// ---------------- NT GEMM via tensor cores (3xTF32 compensated) ---------------
// C[m,n] = alpha * sum_k A[m,k]*B[n,k].  BM=BN=128, BK=16, 256 threads (8 warps
// in 2(M)x4(N)); each warp owns a 64x32 tile = 4x4 grid of m16n8k8 mmas.
__global__ __launch_bounds__(256) void gemm_tf32(const float* __restrict__ A,
                                                 const float* __restrict__ B,
                                                 float* __restrict__ C,
                                                 int M, int N, int K, float alpha) {
    __shared__ float As[128][20];
    __shared__ float Bs[128][20];
    const int tid  = threadIdx.x;
    const int lane = tid & 31;
    const int w    = tid >> 5;
    const int warp_m = (w & 1) * 64;       // 0 or 64
    const int warp_n = (w >> 1) * 32;      // 0,32,64,96
    const int lr = lane >> 2;              // 0..7
    const int lc = lane & 3;               // 0..3
    const int bm0 = blockIdx.y * 128, bn0 = blockIdx.x * 128;

    // staging: each thread stages 2 float4 per matrix per k-tile
    const int ldr  = tid >> 2;             // 0..63
    const int ldr2 = ldr + 64;
    const int ldc  = (tid & 3) << 2;

    float acc[4][4][4];                    // [mt][nt][4]
#pragma unroll
    for (int i = 0; i < 4; i++)
#pragma unroll
        for (int j = 0; j < 4; j++)
#pragma unroll
            for (int r = 0; r < 4; r++) acc[i][j][r] = 0.f;

    // prefetch first k-tile into registers
    float4 ra0 = *(const float4*)&A[(size_t)(bm0 + ldr ) * K + ldc];
    float4 ra1 = *(const float4*)&A[(size_t)(bm0 + ldr2) * K + ldc];
    float4 rb0 = *(const float4*)&B[(size_t)(bn0 + ldr ) * K + ldc];
    float4 rb1 = *(const float4*)&B[(size_t)(bn0 + ldr2) * K + ldc];

    for (int k0 = 0; k0 < K; k0 += 16) {
        *(float4*)&As[ldr ][ldc] = ra0;
        *(float4*)&As[ldr2][ldc] = ra1;
        *(float4*)&Bs[ldr ][ldc] = rb0;
        *(float4*)&Bs[ldr2][ldc] = rb1;
        __syncthreads();

        if (k0 + 16 < K) {
            int kn = k0 + 16;
            ra0 = *(const float4*)&A[(size_t)(bm0 + ldr ) * K + kn + ldc];
            ra1 = *(const float4*)&A[(size_t)(bm0 + ldr2) * K + kn + ldc];
            rb0 = *(const float4*)&B[(size_t)(bn0 + ldr ) * K + kn + ldc];
            rb1 = *(const float4*)&B[(size_t)(bn0 + ldr2) * K + kn + ldc];
        }

#pragma unroll
        for (int ks = 0; ks < 16; ks += 8) {
            // B fragments for all 4 nt tiles: b0 at (k=lc, n=lr), b1 at (k=lc+4, n=lr)
            uint32_t bh[4][2], bl[4][2];
#pragma unroll
            for (int nt = 0; nt < 4; nt++) {
                float b0 = Bs[warp_n + nt * 8 + lr][ks + lc];
                float b1 = Bs[warp_n + nt * 8 + lr][ks + lc + 4];
                bh[nt][0] = f2tf32(b0); bl[nt][0] = __float_as_uint(b0 - __uint_as_float(bh[nt][0]));
                bh[nt][1] = f2tf32(b1); bl[nt][1] = __float_as_uint(b1 - __uint_as_float(bh[nt][1]));
            }
#pragma unroll
            for (int mt = 0; mt < 4; mt++) {
                int r0 = warp_m + mt * 16 + lr;
                float a0 = As[r0    ][ks + lc];
                float a1 = As[r0 + 8][ks + lc];
                float a2 = As[r0    ][ks + lc + 4];
                float a3 = As[r0 + 8][ks + lc + 4];
                uint32_t ah0 = f2tf32(a0), ah1 = f2tf32(a1), ah2 = f2tf32(a2), ah3 = f2tf32(a3);
                uint32_t al0 = __float_as_uint(a0 - __uint_as_float(ah0));
                uint32_t al1 = __float_as_uint(a1 - __uint_as_float(ah1));
                uint32_t al2 = __float_as_uint(a2 - __uint_as_float(ah2));
                uint32_t al3 = __float_as_uint(a3 - __uint_as_float(ah3));
#pragma unroll
                for (int nt = 0; nt < 4; nt++) {
                    mma_tf32(acc[mt][nt], ah0, ah1, ah2, ah3, bh[nt][0], bh[nt][1]);
                    mma_tf32(acc[mt][nt], ah0, ah1, ah2, ah3, bl[nt][0], bl[nt][1]);
                    mma_tf32(acc[mt][nt], al0, al1, al2, al3, bh[nt][0], bh[nt][1]);
                }
            }
        }
        __syncthreads();
    }

    // epilogue: c0,c1 at (row lr, col lc*2 +0/1), c2,c3 at (row lr+8, ...)
#pragma unroll
    for (int mt = 0; mt < 4; mt++) {
#pragma unroll
        for (int nt = 0; nt < 4; nt++) {
            int row = bm0 + warp_m + mt * 16 + lr;
            int col = bn0 + warp_n + nt * 8 + lc * 2;
            float2 lo = make_float2(alpha * acc[mt][nt][0], alpha * acc[mt][nt][1]);
            float2 hi = make_float2(alpha * acc[mt][nt][2], alpha * acc[mt][nt][3]);
            *(float2*)&C[(size_t)row * N + col]       = lo;
            *(float2*)&C[(size_t)(row + 8) * N + col] = hi;
        }
    }
}

// ---------------- flash attention (one attn head, causal) --------------------
// grid: (S/64, NHEAD, BATCH). 256 threads (16x16). BM=BN=64.
// smem: Qs[64][68] Ks[64][68] Ps[64][68] Vs[64][132]  = 86016 bytes
#define FLASH_SMEM_FLOATS (3 * 64 * 68 + 64 * 132)
#define FLASH_SMEM_BYTES  (FLASH_SMEM_FLOATS * 4)

__global__ __launch_bounds__(256) void flash_kernel(const float* __restrict__ q,
                                                    const float* __restrict__ k,
                                                    const float* __restrict__ v,
                                                    float* __restrict__ oj) {
    extern __shared__ float sm[];
    float (*Qs)[68]  = (float (*)[68])sm;
    float (*Ks)[68]  = (float (*)[68])(sm + 64 * 68);
    float (*Ps)[68]  = (float (*)[68])(sm + 2 * 64 * 68);
    float (*Vs)[132] = (float (*)[132])(sm + 3 * 64 * 68);

    const int tid = threadIdx.x;
    const int ty = tid >> 4, tx = tid & 15;
    const int qb = blockIdx.x;      // query block (64 rows)
    const int h  = blockIdx.y;      // attn head 0..15
    const int b  = blockIdx.z;
    const int hv = h >> 1;

    const float* qbase = q + ((size_t)(b * S_LEN + qb * 64)) * DIMN + h * HD;
    const float* kbase = k + (size_t)b * S_LEN * DIMN + h * HD;
    const float* vbase = v + (size_t)b * S_LEN * DIMN + hv * VD;

    // load Q tile: 64 rows x 64 floats (16 float4/row)
#pragma unroll
    for (int u = 0; u < 4; u++) {
        int idx = tid + u * 256;        // 0..1023
        int row = idx >> 4;
        int c4  = (idx & 15) << 2;
        *(float4*)&Qs[row][c4] = *(const float4*)&qbase[(size_t)row * DIMN + c4];
    }

    float m[4], l[4], o[4][8];
#pragma unroll
    for (int i = 0; i < 4; i++) {
        m[i] = -1e30f; l[i] = 0.f;
#pragma unroll
        for (int j = 0; j < 8; j++) o[i][j] = 0.f;
    }

    for (int kt = 0; kt <= qb; kt++) {
        __syncthreads();   // also orders Q-tile writes before first compute
        // load K tile (64x64) and V tile (64x128)
#pragma unroll
        for (int u = 0; u < 4; u++) {
            int idx = tid + u * 256;
            int row = idx >> 4;
            int c4  = (idx & 15) << 2;
            *(float4*)&Ks[row][c4] = *(const float4*)&kbase[(size_t)(kt * 64 + row) * DIMN + c4];
        }
#pragma unroll
        for (int u = 0; u < 8; u++) {
            int idx = tid + u * 256;    // 0..2047
            int row = idx >> 5;
            int c4  = (idx & 31) << 2;
            *(float4*)&Vs[row][c4] = *(const float4*)&vbase[(size_t)(kt * 64 + row) * DIMN + c4];
        }
        __syncthreads();

        // S = Q K^T  (q already scaled by 1/8)
        float s[4][4];
#pragma unroll
        for (int i = 0; i < 4; i++)
#pragma unroll
            for (int j = 0; j < 4; j++) s[i][j] = 0.f;
#pragma unroll
        for (int kk = 0; kk < 64; kk += 4) {
            float4 a[4], bb[4];
#pragma unroll
            for (int i = 0; i < 4; i++) a[i]  = *(float4*)&Qs[ty + 16 * i][kk];
#pragma unroll
            for (int j = 0; j < 4; j++) bb[j] = *(float4*)&Ks[tx + 16 * j][kk];
#pragma unroll
            for (int i = 0; i < 4; i++)
#pragma unroll
                for (int j = 0; j < 4; j++)
                    s[i][j] += a[i].x*bb[j].x + a[i].y*bb[j].y + a[i].z*bb[j].z + a[i].w*bb[j].w;
        }
        if (kt == qb) {
#pragma unroll
            for (int i = 0; i < 4; i++)
#pragma unroll
                for (int j = 0; j < 4; j++)
                    if ((tx + 16 * j) > (ty + 16 * i)) s[i][j] = -1e30f;
        }

        // online softmax per row (row owned by 16 tx-threads; shfl width 16)
#pragma unroll
        for (int i = 0; i < 4; i++) {
            float mt = s[i][0];
#pragma unroll
            for (int j = 1; j < 4; j++) mt = fmaxf(mt, s[i][j]);
#pragma unroll
            for (int off = 8; off > 0; off >>= 1)
                mt = fmaxf(mt, __shfl_xor_sync(0xffffffffu, mt, off, 16));
            float mn = fmaxf(m[i], mt);
            float sc = __expf(m[i] - mn);
            float ps = 0.f;
#pragma unroll
            for (int j = 0; j < 4; j++) { s[i][j] = __expf(s[i][j] - mn); ps += s[i][j]; }
#pragma unroll
            for (int off = 8; off > 0; off >>= 1)
                ps += __shfl_xor_sync(0xffffffffu, ps, off, 16);
            l[i] = l[i] * sc + ps;
#pragma unroll
            for (int j = 0; j < 8; j++) o[i][j] *= sc;
            m[i] = mn;
#pragma unroll
            for (int j = 0; j < 4; j++) Ps[ty + 16 * i][tx + 16 * j] = s[i][j];
        }
        __syncthreads();

        // O += P @ V   (O cols: tx*4..+3 and 64+tx*4..+3)
#pragma unroll
        for (int kk = 0; kk < 64; kk += 4) {
            float4 p4[4];
#pragma unroll
            for (int i = 0; i < 4; i++) p4[i] = *(float4*)&Ps[ty + 16 * i][kk];
#pragma unroll
            for (int kq = 0; kq < 4; kq++) {
                float4 v0 = *(float4*)&Vs[kk + kq][tx * 4];
                float4 v1 = *(float4*)&Vs[kk + kq][64 + tx * 4];
#pragma unroll
                for (int i = 0; i < 4; i++) {
                    float pk = (kq == 0) ? p4[i].x : (kq == 1) ? p4[i].y : (kq == 2) ? p4[i].z : p4[i].w;
                    o[i][0] += pk * v0.x; o[i][1] += pk * v0.y;
                    o[i][2] += pk * v0.z; o[i][3] += pk * v0.w;
                    o[i][4] += pk * v1.x; o[i][5] += pk * v1.y;
                    o[i][6] += pk * v1.z; o[i][7] += pk * v1.w;
                }
            }
        }
    }

    // epilogue: normalize and store to g_oj[b, h, s, 0:128]
    float* obase = oj + (((size_t)(b * NHEAD + h)) * S_LEN + qb * 64) * VD;
#pragma unroll
    for (int i = 0; i < 4; i++) {
        float inv = 1.f / l[i];
        int row = ty + 16 * i;
        float4 r0 = make_float4(o[i][0]*inv, o[i][1]*inv, o[i][2]*inv, o[i][3]*inv);
        float4 r1 = make_float4(o[i][4]*inv, o[i][5]*inv, o[i][6]*inv, o[i][7]*inv);
        *(float4*)&obase[(size_t)row * VD + tx * 4]      = r0;
        *(float4*)&obase[(size_t)row * VD + 64 + tx * 4] = r1;
    }
}

// ---------------- combine pairs + RMSNorm -------------------------------------
// grid: B*S*8 blocks of 128 threads. block -> (b, s, hv); thread -> d in [0,128)
__global__ void combine_kernel(const float* __restrict__ oj, float* __restrict__ att) {
    const int bid = blockIdx.x;
    const int hv = bid & 7;
    const int s  = (bid >> 3) & (S_LEN - 1);
    const int b  = bid >> 14;
    const int d  = threadIdx.x;

    const float lam = g_lambda;
    size_t i0 = (((size_t)(b * NHEAD + 2 * hv)) * S_LEN + s) * VD + d;
    size_t i1 = i0 + (size_t)S_LEN * VD;
    float val = oj[i0] - lam * oj[i1];

    float v2 = val * val;
#pragma unroll
    for (int off = 16; off > 0; off >>= 1)
        v2 += __shfl_xor_sync(0xffffffffu, v2, off);
    __shared__ float red[4];
    if ((d & 31) == 0) red[d >> 5] = v2;
    __syncthreads();
    float tot = red[0] + red[1] + red[2] + red[3];
    float rms = rsqrtf(tot * (1.0f / 128.0f) + 1e-5f);
    att[((size_t)(b * S_LEN) + s) * DIMN + hv * VD + d] = val * rms * (1.0f - LAMBDA_INIT);
}

// ---------------- launch ------------------------------------------------------
extern "C" void kernel_launch(void* const* d_in, const int* in_sizes, int n_in,
                              void* d_out, int out_size) {
    const float* x   = (const float*)d_in[0];
    const float* Wq  = (const float*)d_in[1];
    const float* Wk  = (const float*)d_in[2];
    const float* Wv  = (const float*)d_in[3];
    const float* Wo  = (const float*)d_in[4];
    const float* lq1 = (const float*)d_in[5];
    const float* lk1 = (const float*)d_in[6];
    const float* lq2 = (const float*)d_in[7];
    const float* lk2 = (const float*)d_in[8];
    float* out = (float*)d_out;

    float *q_p, *k_p, *v_p, *oj_p, *att_p;
    cudaGetSymbolAddress((void**)&q_p,   g_q);
    cudaGetSymbolAddress((void**)&k_p,   g_k);
    cudaGetSymbolAddress((void**)&v_p,   g_v);
    cudaGetSymbolAddress((void**)&oj_p,  g_oj);
    cudaGetSymbolAddress((void**)&att_p, g_att);

    cudaFuncSetAttribute(flash_kernel, cudaFuncAttributeMaxDynamicSharedMemorySize,
                         FLASH_SMEM_BYTES);

    lambda_kernel<<<1, 32>>>(lq1, lk1, lq2, lk2);

    dim3 ggrid(DIMN / 128, M_TOT / 128);
    gemm_tf32<<<ggrid, 256>>>(x, Wq, q_p, M_TOT, DIMN, DIMN, 0.125f);  // hd^-0.5
    gemm_tf32<<<ggrid, 256>>>(x, Wk, k_p, M_TOT, DIMN, DIMN, 1.0f);
    gemm_tf32<<<ggrid, 256>>>(x, Wv, v_p, M_TOT, DIMN, DIMN, 1.0f);

    dim3 fgrid(S_LEN / 64, NHEAD, BATCH);
    flash_kernel<<<fgrid, 256, FLASH_SMEM_BYTES>>>(q_p, k_p, v_p, oj_p);

    combine_kernel<<<BATCH * S_LEN * 8, 128>>>(oj_p, att_p);

    gemm_tf32<<<ggrid, 256>>>(att_p, Wo, out, M_TOT, DIMN, DIMN, 1.0f);
}

// round 10
// speedup vs baseline: 2.4838x; 1.2786x over previous
#include <cuda_runtime.h>
#include <math.h>
#include <stdint.h>

#define DIMN   1024
#define S_LEN  2048
#define BATCH  2
#define NHEAD  16     // 2H attention heads (q/k), dim 64
#define HD     64
#define VD     128    // v head dim (2*hd)
#define M_TOT  (BATCH*S_LEN)   // 4096

#define LAMBDA_INIT 0.70082066706704805f

// ---------------- scratch (static device memory; no runtime allocs) ----------
__device__ float g_q[(size_t)BATCH*S_LEN*DIMN];
__device__ float g_k[(size_t)BATCH*S_LEN*DIMN];
__device__ float g_v[(size_t)BATCH*S_LEN*DIMN];
__device__ float g_oj[(size_t)BATCH*NHEAD*S_LEN*VD];   // per-attn-head O
__device__ float g_att[(size_t)BATCH*S_LEN*DIMN];      // combined, pre-Wo
__device__ float g_lambda;

// ---------------- lambda ------------------------------------------------------
__global__ void lambda_kernel(const float* __restrict__ lq1, const float* __restrict__ lk1,
                              const float* __restrict__ lq2, const float* __restrict__ lk2) {
    if (threadIdx.x == 0) {
        float s1 = 0.f, s2 = 0.f;
        for (int i = 0; i < HD; i++) { s1 += lq1[i]*lk1[i]; s2 += lq2[i]*lk2[i]; }
        g_lambda = expf(s1) - expf(s2) + LAMBDA_INIT;
    }
}

// ---------------- tf32 mma helpers -------------------------------------------
__device__ __forceinline__ uint32_t f2tf32(float x) {
    uint32_t r;
    asm("cvt.rna.tf32.f32 %0, %1;" : "=r"(r) : "f"(x));
    return r;
}
__device__ __forceinline__ float tf32hi(float x) {
    return __uint_as_float(f2tf32(x));
}

__device__ __forceinline__ void mma_tf32(float* c,
                                         uint32_t a0, uint32_t a1, uint32_t a2, uint32_t a3,
                                         uint32_t b0, uint32_t b1) {
    asm volatile("mma.sync.aligned.m16n8k8.row.col.f32.tf32.tf32.f32 "
                 "{%0,%1,%2,%3}, {%4,%5,%6,%7}, {%8,%9}, {%0,%1,%2,%3};\n"
                 : "+f"(c[0]), "+f"(c[1]), "+f"(c[2]), "+f"(c[3])
                 : "r"(a0), "r"(a1), "r"(a2), "r"(a3), "r"(b0), "r"(b1));
}

// ---------------- NT GEMM via tensor cores (3xTF32, pre-split smem) -----------
// C[m,n] = alpha * sum_k A[m,k]*B[n,k].  BM=BN=128, BK=16, 256 threads (8 warps
// in 2(M)x4(N)); each warp owns a 64x32 tile = 4x4 grid of m16n8k8 mmas.
__global__ __launch_bounds__(256) void gemm_tf32(const float* __restrict__ A,
                                                 const float* __restrict__ B,
                                                 float* __restrict__ C,
                                                 int M, int N, int K, float alpha) {
    __shared__ float Ash[128][20], Asl[128][20];
    __shared__ float Bsh[128][20], Bsl[128][20];
    const int tid  = threadIdx.x;
    const int lane = tid & 31;
    const int w    = tid >> 5;
    const int warp_m = (w & 1) * 64;       // 0 or 64
    const int warp_n = (w >> 1) * 32;      // 0,32,64,96
    const int lr = lane >> 2;              // 0..7
    const int lc = lane & 3;               // 0..3
    const int bm0 = blockIdx.y * 128, bn0 = blockIdx.x * 128;

    const int ldr  = tid >> 2;             // 0..63
    const int ldr2 = ldr + 64;
    const int ldc  = (tid & 3) << 2;

    float acc[4][4][4];
#pragma unroll
    for (int i = 0; i < 4; i++)
#pragma unroll
        for (int j = 0; j < 4; j++)
#pragma unroll
            for (int r = 0; r < 4; r++) acc[i][j][r] = 0.f;

    float4 ra0 = *(const float4*)&A[(size_t)(bm0 + ldr ) * K + ldc];
    float4 ra1 = *(const float4*)&A[(size_t)(bm0 + ldr2) * K + ldc];
    float4 rb0 = *(const float4*)&B[(size_t)(bn0 + ldr ) * K + ldc];
    float4 rb1 = *(const float4*)&B[(size_t)(bn0 + ldr2) * K + ldc];

    for (int k0 = 0; k0 < K; k0 += 16) {
        {
            float4 h, l;
            h.x=tf32hi(ra0.x); h.y=tf32hi(ra0.y); h.z=tf32hi(ra0.z); h.w=tf32hi(ra0.w);
            l.x=ra0.x-h.x; l.y=ra0.y-h.y; l.z=ra0.z-h.z; l.w=ra0.w-h.w;
            *(float4*)&Ash[ldr][ldc] = h; *(float4*)&Asl[ldr][ldc] = l;
            h.x=tf32hi(ra1.x); h.y=tf32hi(ra1.y); h.z=tf32hi(ra1.z); h.w=tf32hi(ra1.w);
            l.x=ra1.x-h.x; l.y=ra1.y-h.y; l.z=ra1.z-h.z; l.w=ra1.w-h.w;
            *(float4*)&Ash[ldr2][ldc] = h; *(float4*)&Asl[ldr2][ldc] = l;
            h.x=tf32hi(rb0.x); h.y=tf32hi(rb0.y); h.z=tf32hi(rb0.z); h.w=tf32hi(rb0.w);
            l.x=rb0.x-h.x; l.y=rb0.y-h.y; l.z=rb0.z-h.z; l.w=rb0.w-h.w;
            *(float4*)&Bsh[ldr][ldc] = h; *(float4*)&Bsl[ldr][ldc] = l;
            h.x=tf32hi(rb1.x); h.y=tf32hi(rb1.y); h.z=tf32hi(rb1.z); h.w=tf32hi(rb1.w);
            l.x=rb1.x-h.x; l.y=rb1.y-h.y; l.z=rb1.z-h.z; l.w=rb1.w-h.w;
            *(float4*)&Bsh[ldr2][ldc] = h; *(float4*)&Bsl[ldr2][ldc] = l;
        }
        __syncthreads();

        if (k0 + 16 < K) {
            int kn = k0 + 16;
            ra0 = *(const float4*)&A[(size_t)(bm0 + ldr ) * K + kn + ldc];
            ra1 = *(const float4*)&A[(size_t)(bm0 + ldr2) * K + kn + ldc];
            rb0 = *(const float4*)&B[(size_t)(bn0 + ldr ) * K + kn + ldc];
            rb1 = *(const float4*)&B[(size_t)(bn0 + ldr2) * K + kn + ldc];
        }

#pragma unroll
        for (int ks = 0; ks < 16; ks += 8) {
            uint32_t bh[4][2], bl[4][2];
#pragma unroll
            for (int nt = 0; nt < 4; nt++) {
                int rn = warp_n + nt * 8 + lr;
                bh[nt][0] = __float_as_uint(Bsh[rn][ks + lc]);
                bh[nt][1] = __float_as_uint(Bsh[rn][ks + lc + 4]);
                bl[nt][0] = __float_as_uint(Bsl[rn][ks + lc]);
                bl[nt][1] = __float_as_uint(Bsl[rn][ks + lc + 4]);
            }
#pragma unroll
            for (int mt = 0; mt < 4; mt++) {
                int r0 = warp_m + mt * 16 + lr;
                uint32_t ah0 = __float_as_uint(Ash[r0    ][ks + lc]);
                uint32_t ah1 = __float_as_uint(Ash[r0 + 8][ks + lc]);
                uint32_t ah2 = __float_as_uint(Ash[r0    ][ks + lc + 4]);
                uint32_t ah3 = __float_as_uint(Ash[r0 + 8][ks + lc + 4]);
                uint32_t al0 = __float_as_uint(Asl[r0    ][ks + lc]);
                uint32_t al1 = __float_as_uint(Asl[r0 + 8][ks + lc]);
                uint32_t al2 = __float_as_uint(Asl[r0    ][ks + lc + 4]);
                uint32_t al3 = __float_as_uint(Asl[r0 + 8][ks + lc + 4]);
#pragma unroll
                for (int nt = 0; nt < 4; nt++) {
                    mma_tf32(acc[mt][nt], ah0, ah1, ah2, ah3, bh[nt][0], bh[nt][1]);
                    mma_tf32(acc[mt][nt], ah0, ah1, ah2, ah3, bl[nt][0], bl[nt][1]);
                    mma_tf32(acc[mt][nt], al0, al1, al2, al3, bh[nt][0], bh[nt][1]);
                }
            }
        }
        __syncthreads();
    }

#pragma unroll
    for (int mt = 0; mt < 4; mt++) {
#pragma unroll
        for (int nt = 0; nt < 4; nt++) {
            int row = bm0 + warp_m + mt * 16 + lr;
            int col = bn0 + warp_n + nt * 8 + lc * 2;
            float2 lo = make_float2(alpha * acc[mt][nt][0], alpha * acc[mt][nt][1]);
            float2 hi = make_float2(alpha * acc[mt][nt][2], alpha * acc[mt][nt][3]);
            *(float2*)&C[(size_t)row * N + col]       = lo;
            *(float2*)&C[(size_t)(row + 8) * N + col] = hi;
        }
    }
}

// ---------------- flash attention, tensor-core version ------------------------
// BM=128 q rows, BN=64 keys/iter, hd=64, VD=128. 256 threads = 8 warps, each
// warp owns 16 q rows (softmax state warp-local). QK = 3xTF32, PV = 1xTF32.
// smem floats: Qh/Ql 128x68, Kh/Kl 64x68, V 64x136, P 128x68  -> 174080 B
#define FL_QS 68
#define FL_VS 136
#define FLASH_SMEM_FLOATS (2*128*FL_QS + 2*64*FL_QS + 64*FL_VS + 128*FL_QS)
#define FLASH_SMEM_BYTES  (FLASH_SMEM_FLOATS * 4)

__global__ __launch_bounds__(256, 1) void flash_mma_kernel(const float* __restrict__ q,
                                                           const float* __restrict__ k,
                                                           const float* __restrict__ v,
                                                           float* __restrict__ oj) {
    extern __shared__ float sm[];
    float (*Qh)[FL_QS] = (float (*)[FL_QS])sm;
    float (*Ql)[FL_QS] = (float (*)[FL_QS])(sm + 128 * FL_QS);
    float (*Kh)[FL_QS] = (float (*)[FL_QS])(sm + 2 * 128 * FL_QS);
    float (*Kl)[FL_QS] = (float (*)[FL_QS])(sm + 2 * 128 * FL_QS + 64 * FL_QS);
    float (*Vs)[FL_VS] = (float (*)[FL_VS])(sm + 2 * 128 * FL_QS + 2 * 64 * FL_QS);
    float (*Ps)[FL_QS] = (float (*)[FL_QS])(sm + 2 * 128 * FL_QS + 2 * 64 * FL_QS + 64 * FL_VS);

    const int tid  = threadIdx.x;
    const int lane = tid & 31;
    const int w    = tid >> 5;
    const int wm   = w * 16;               // warp's 16 q rows
    const int lr   = lane >> 2;            // 0..7
    const int lc   = lane & 3;             // 0..3
    const int qb   = (gridDim.x - 1) - blockIdx.x;   // big tiles first
    const int h    = blockIdx.y;
    const int b    = blockIdx.z;
    const int hv   = h >> 1;

    const float* qbase = q + ((size_t)(b * S_LEN + qb * 128)) * DIMN + h * HD;
    const float* kbase = k + (size_t)b * S_LEN * DIMN + h * HD;
    const float* vbase = v + (size_t)b * S_LEN * DIMN + hv * VD;

    // load Q tile 128x64, split hi/lo. 2048 float4, 8 per thread.
#pragma unroll
    for (int u = 0; u < 8; u++) {
        int idx = tid + u * 256;
        int row = idx >> 4;
        int c4  = (idx & 15) << 2;
        float4 x = *(const float4*)&qbase[(size_t)row * DIMN + c4];
        float4 hh, ll;
        hh.x=tf32hi(x.x); hh.y=tf32hi(x.y); hh.z=tf32hi(x.z); hh.w=tf32hi(x.w);
        ll.x=x.x-hh.x; ll.y=x.y-hh.y; ll.z=x.z-hh.z; ll.w=x.w-hh.w;
        *(float4*)&Qh[row][c4] = hh;
        *(float4*)&Ql[row][c4] = ll;
    }

    float mrow[2], lrow[2];
    float o[16][4];
    mrow[0] = mrow[1] = -1e30f;
    lrow[0] = lrow[1] = 0.f;
#pragma unroll
    for (int i = 0; i < 16; i++)
#pragma unroll
        for (int r = 0; r < 4; r++) o[i][r] = 0.f;

    const int ktiles = 2 * qb + 2;
    for (int kt = 0; kt < ktiles; kt++) {
        __syncthreads();
        // load K tile 64x64 (split hi/lo): 1024 float4, 4/thread
#pragma unroll
        for (int u = 0; u < 4; u++) {
            int idx = tid + u * 256;
            int row = idx >> 4;
            int c4  = (idx & 15) << 2;
            float4 x = *(const float4*)&kbase[(size_t)(kt * 64 + row) * DIMN + c4];
            float4 hh, ll;
            hh.x=tf32hi(x.x); hh.y=tf32hi(x.y); hh.z=tf32hi(x.z); hh.w=tf32hi(x.w);
            ll.x=x.x-hh.x; ll.y=x.y-hh.y; ll.z=x.z-hh.z; ll.w=x.w-hh.w;
            *(float4*)&Kh[row][c4] = hh;
            *(float4*)&Kl[row][c4] = ll;
        }
        // load V tile 64x128 (tf32-rounded): 2048 float4, 8/thread
#pragma unroll
        for (int u = 0; u < 8; u++) {
            int idx = tid + u * 256;
            int row = idx >> 5;
            int c4  = (idx & 31) << 2;
            float4 x = *(const float4*)&vbase[(size_t)(kt * 64 + row) * DIMN + c4];
            x.x=tf32hi(x.x); x.y=tf32hi(x.y); x.z=tf32hi(x.z); x.w=tf32hi(x.w);
            *(float4*)&Vs[row][c4] = x;
        }
        __syncthreads();

        // ---- S = Q K^T via 3xTF32: 8 n8-tiles x 8 k-steps ----
        float s[8][4];
#pragma unroll
        for (int nt = 0; nt < 8; nt++)
#pragma unroll
            for (int r = 0; r < 4; r++) s[nt][r] = 0.f;

#pragma unroll
        for (int ks = 0; ks < 64; ks += 8) {
            int r0 = wm + lr;
            uint32_t ah0 = __float_as_uint(Qh[r0    ][ks + lc]);
            uint32_t ah1 = __float_as_uint(Qh[r0 + 8][ks + lc]);
            uint32_t ah2 = __float_as_uint(Qh[r0    ][ks + lc + 4]);
            uint32_t ah3 = __float_as_uint(Qh[r0 + 8][ks + lc + 4]);
            uint32_t al0 = __float_as_uint(Ql[r0    ][ks + lc]);
            uint32_t al1 = __float_as_uint(Ql[r0 + 8][ks + lc]);
            uint32_t al2 = __float_as_uint(Ql[r0    ][ks + lc + 4]);
            uint32_t al3 = __float_as_uint(Ql[r0 + 8][ks + lc + 4]);
#pragma unroll
            for (int nt = 0; nt < 8; nt++) {
                int rn = nt * 8 + lr;
                uint32_t bh0 = __float_as_uint(Kh[rn][ks + lc]);
                uint32_t bh1 = __float_as_uint(Kh[rn][ks + lc + 4]);
                uint32_t bl0 = __float_as_uint(Kl[rn][ks + lc]);
                uint32_t bl1 = __float_as_uint(Kl[rn][ks + lc + 4]);
                mma_tf32(s[nt], ah0, ah1, ah2, ah3, bh0, bh1);
                mma_tf32(s[nt], ah0, ah1, ah2, ah3, bl0, bl1);
                mma_tf32(s[nt], al0, al1, al2, al3, bh0, bh1);
            }
        }

        // ---- causal mask on diagonal tiles ----
        if (kt >= 2 * qb) {
            int koff = kt * 64 - qb * 128;   // 0 or 64
            int r0 = wm + lr, r1 = wm + lr + 8;
#pragma unroll
            for (int nt = 0; nt < 8; nt++) {
                int c0 = koff + nt * 8 + lc * 2;
                int c1 = c0 + 1;
                if (c0 > r0) s[nt][0] = -1e30f;
                if (c1 > r0) s[nt][1] = -1e30f;
                if (c0 > r1) s[nt][2] = -1e30f;
                if (c1 > r1) s[nt][3] = -1e30f;
            }
        }

        // ---- online softmax (rows lr and lr+8, quad-wide reductions) ----
#pragma unroll
        for (int half = 0; half < 2; half++) {
            float mt = -1e30f;
#pragma unroll
            for (int nt = 0; nt < 8; nt++)
                mt = fmaxf(mt, fmaxf(s[nt][2*half], s[nt][2*half+1]));
            mt = fmaxf(mt, __shfl_xor_sync(0xffffffffu, mt, 1));
            mt = fmaxf(mt, __shfl_xor_sync(0xffffffffu, mt, 2));
            float mn = fmaxf(mrow[half], mt);
            float sc = __expf(mrow[half] - mn);
            float ps = 0.f;
#pragma unroll
            for (int nt = 0; nt < 8; nt++) {
                float e0 = __expf(s[nt][2*half]   - mn);
                float e1 = __expf(s[nt][2*half+1] - mn);
                ps += e0 + e1;
                s[nt][2*half]   = e0;
                s[nt][2*half+1] = e1;
            }
            ps += __shfl_xor_sync(0xffffffffu, ps, 1);
            ps += __shfl_xor_sync(0xffffffffu, ps, 2);
            lrow[half] = lrow[half] * sc + ps;
            mrow[half] = mn;
#pragma unroll
            for (int nt = 0; nt < 16; nt++) {
                o[nt][2*half]   *= sc;
                o[nt][2*half+1] *= sc;
            }
        }

        // ---- stage P (tf32-rounded) to this warp's smem rows ----
        {
            int r0 = wm + lr, r1 = wm + lr + 8;
#pragma unroll
            for (int nt = 0; nt < 8; nt++) {
                int c = nt * 8 + lc * 2;
                Ps[r0][c]     = tf32hi(s[nt][0]);
                Ps[r0][c + 1] = tf32hi(s[nt][1]);
                Ps[r1][c]     = tf32hi(s[nt][2]);
                Ps[r1][c + 1] = tf32hi(s[nt][3]);
            }
        }
        __syncwarp();

        // ---- O += P @ V : 16 vd n8-tiles x 8 k-steps ----
#pragma unroll
        for (int ks = 0; ks < 64; ks += 8) {
            int r0 = wm + lr;
            uint32_t a0 = __float_as_uint(Ps[r0    ][ks + lc]);
            uint32_t a1 = __float_as_uint(Ps[r0 + 8][ks + lc]);
            uint32_t a2 = __float_as_uint(Ps[r0    ][ks + lc + 4]);
            uint32_t a3 = __float_as_uint(Ps[r0 + 8][ks + lc + 4]);
#pragma unroll
            for (int nt = 0; nt < 16; nt++) {
                uint32_t b0 = __float_as_uint(Vs[ks + lc    ][nt * 8 + lr]);
                uint32_t b1 = __float_as_uint(Vs[ks + lc + 4][nt * 8 + lr]);
                mma_tf32(o[nt], a0, a1, a2, a3, b0, b1);
            }
        }
    }

    // ---- epilogue: O /= l, store ----
    float* obase = oj + (((size_t)(b * NHEAD + h)) * S_LEN + qb * 128) * VD;
    float inv0 = 1.f / lrow[0];
    float inv1 = 1.f / lrow[1];
    int r0 = wm + lr, r1 = wm + lr + 8;
#pragma unroll
    for (int nt = 0; nt < 16; nt++) {
        int c = nt * 8 + lc * 2;
        *(float2*)&obase[(size_t)r0 * VD + c] = make_float2(o[nt][0] * inv0, o[nt][1] * inv0);
        *(float2*)&obase[(size_t)r1 * VD + c] = make_float2(o[nt][2] * inv1, o[nt][3] * inv1);
    }
}

// ---------------- combine pairs + RMSNorm -------------------------------------
__global__ void combine_kernel(const float* __restrict__ oj, float* __restrict__ att) {
    const int bid = blockIdx.x;
    const int hv = bid & 7;
    const int s  = (bid >> 3) & (S_LEN - 1);
    const int b  = bid >> 14;
    const int d  = threadIdx.x;

    const float lam = g_lambda;
    size_t i0 = (((size_t)(b * NHEAD + 2 * hv)) * S_LEN + s) * VD + d;
    size_t i1 = i0 + (size_t)S_LEN * VD;
    float val = oj[i0] - lam * oj[i1];

    float v2 = val * val;
#pragma unroll
    for (int off = 16; off > 0; off >>= 1)
        v2 += __shfl_xor_sync(0xffffffffu, v2, off);
    __shared__ float red[4];
    if ((d & 31) == 0) red[d >> 5] = v2;
    __syncthreads();
    float tot = red[0] + red[1] + red[2] + red[3];
    float rms = rsqrtf(tot * (1.0f / 128.0f) + 1e-5f);
    att[((size_t)(b * S_LEN) + s) * DIMN + hv * VD + d] = val * rms * (1.0f - LAMBDA_INIT);
}

// ---------------- launch ------------------------------------------------------
extern "C" void kernel_launch(void* const* d_in, const int* in_sizes, int n_in,
                              void* d_out, int out_size) {
    const float* x   = (const float*)d_in[0];
    const float* Wq  = (const float*)d_in[1];
    const float* Wk  = (const float*)d_in[2];
    const float* Wv  = (const float*)d_in[3];
    const float* Wo  = (const float*)d_in[4];
    const float* lq1 = (const float*)d_in[5];
    const float* lk1 = (const float*)d_in[6];
    const float* lq2 = (const float*)d_in[7];
    const float* lk2 = (const float*)d_in[8];
    float* out = (float*)d_out;

    float *q_p, *k_p, *v_p, *oj_p, *att_p;
    cudaGetSymbolAddress((void**)&q_p,   g_q);
    cudaGetSymbolAddress((void**)&k_p,   g_k);
    cudaGetSymbolAddress((void**)&v_p,   g_v);
    cudaGetSymbolAddress((void**)&oj_p,  g_oj);
    cudaGetSymbolAddress((void**)&att_p, g_att);

    cudaFuncSetAttribute(flash_mma_kernel, cudaFuncAttributeMaxDynamicSharedMemorySize,
                         FLASH_SMEM_BYTES);

    lambda_kernel<<<1, 32>>>(lq1, lk1, lq2, lk2);

    dim3 ggrid(DIMN / 128, M_TOT / 128);
    gemm_tf32<<<ggrid, 256>>>(x, Wq, q_p, M_TOT, DIMN, DIMN, 0.125f);  // hd^-0.5
    gemm_tf32<<<ggrid, 256>>>(x, Wk, k_p, M_TOT, DIMN, DIMN, 1.0f);
    gemm_tf32<<<ggrid, 256>>>(x, Wv, v_p, M_TOT, DIMN, DIMN, 1.0f);

    dim3 fgrid(S_LEN / 128, NHEAD, BATCH);
    flash_mma_kernel<<<fgrid, 256, FLASH_SMEM_BYTES>>>(q_p, k_p, v_p, oj_p);

    combine_kernel<<<BATCH * S_LEN * 8, 128>>>(oj_p, att_p);

    gemm_tf32<<<ggrid, 256>>>(att_p, Wo, out, M_TOT, DIMN, DIMN, 1.0f);
}